// round 2
// baseline (speedup 1.0000x reference)
#include <cuda_runtime.h>
#include <float.h>

// Problem constants
#define B_   4
#define N_   4096
#define K_   16

// Scratch (allocation-free rule: __device__ globals)
__device__ int   g_knn_idx[B_ * N_ * K_];
__device__ float g_basis[B_ * N_ * K_ * 20];

// ---------------------------------------------------------------------------
// KNN + Taylor basis.
// One thread per query point. Candidates tiled through shared memory.
// d2 computed exactly like the reference: sq_i + sq_j - 2*dot, with forced
// rounding so self-distance is exactly 0 and ties keep ascending index
// (matches jax.lax.top_k stable ordering).
// ---------------------------------------------------------------------------
__global__ void knn_basis_kernel(const float* __restrict__ pc)
{
    const int b = blockIdx.y;
    const int n = blockIdx.x * 128 + threadIdx.x;
    const float* pcb = pc + (size_t)b * N_ * 6;

    const float qx = pcb[n * 6 + 0];
    const float qy = pcb[n * 6 + 1];
    const float qz = pcb[n * 6 + 2];
    const float qsq = __fadd_rn(__fadd_rn(__fmul_rn(qx, qx), __fmul_rn(qy, qy)),
                                __fmul_rn(qz, qz));

    float dist[K_];
    int   nid[K_];
#pragma unroll
    for (int i = 0; i < K_; i++) { dist[i] = FLT_MAX; nid[i] = 0; }

    __shared__ float4 s_c[1024];

    for (int tile = 0; tile < N_; tile += 1024) {
        __syncthreads();
        for (int i = threadIdx.x; i < 1024; i += 128) {
            int j = tile + i;
            float x = pcb[j * 6 + 0];
            float y = pcb[j * 6 + 1];
            float z = pcb[j * 6 + 2];
            float sq = __fadd_rn(__fadd_rn(__fmul_rn(x, x), __fmul_rn(y, y)),
                                 __fmul_rn(z, z));
            s_c[i] = make_float4(x, y, z, sq);
        }
        __syncthreads();

        for (int i = 0; i < 1024; i++) {
            float4 c = s_c[i];
            float dot = __fadd_rn(__fadd_rn(__fmul_rn(qx, c.x), __fmul_rn(qy, c.y)),
                                  __fmul_rn(qz, c.z));
            float d2 = __fsub_rn(__fadd_rn(qsq, c.w), __fmul_rn(2.0f, dot));
            if (d2 < dist[K_ - 1]) {
                dist[K_ - 1] = d2;
                nid[K_ - 1] = tile + i;
#pragma unroll
                for (int j = K_ - 1; j > 0; --j) {
                    if (dist[j] < dist[j - 1]) {
                        float td = dist[j]; dist[j] = dist[j - 1]; dist[j - 1] = td;
                        int ti = nid[j]; nid[j] = nid[j - 1]; nid[j - 1] = ti;
                    }
                }
            }
        }
    }

    int*   iout = g_knn_idx + ((size_t)b * N_ + n) * K_;
    float* bout = g_basis + (((size_t)b * N_ + n) * K_) * 20;
#pragma unroll
    for (int k = 0; k < K_; k++) {
        int j = nid[k];
        iout[k] = j;
        float x = pcb[j * 6 + 0] - qx;
        float y = pcb[j * 6 + 1] - qy;
        float z = pcb[j * 6 + 2] - qz;
        float* o = bout + k * 20;
        o[0] = 1.0f; o[1] = x; o[2] = y; o[3] = z;
        o[4] = x * x; o[5] = x * y; o[6] = x * z;
        o[7] = y * y; o[8] = y * z; o[9] = z * z;
        o[10] = x * x * x; o[11] = x * x * y; o[12] = x * x * z;
        o[13] = x * y * y; o[14] = x * y * z; o[15] = x * z * z;
        o[16] = y * y * y; o[17] = y * y * z; o[18] = y * z * z;
        o[19] = z * z * z;
    }
}

// ---------------------------------------------------------------------------
// SpiderConv layer: out[b,o,n] = relu( sum_{c,t,k} gf*tay*W + b2 )
// GEMM framing: M=128 points per block, Kdim chunked 48-wide per input
// channel c (t*16+k), N = BN output channels per block.
// E (fused activations) generated on the fly into shared each c-iteration.
// ---------------------------------------------------------------------------
template<int CIN, int COUT, int BN>
__global__ void __launch_bounds__(256, 2)
layer_kernel(const float* __restrict__ feat_in, int strideB, int strideJ, int strideC,
             const float* __restrict__ w1, const float* __restrict__ b1,
             const float* __restrict__ w2, const float* __restrict__ b2,
             float* __restrict__ pf_out)   // base at this layer's channel 0
{
    constexpr int TN = BN / 16;

    extern __shared__ float smem[];
    float* s_tay = smem;                 // [48][128]
    float* s_E   = s_tay + 48 * 128;     // [48][128]
    float* s_W   = s_E + 48 * 128;       // [BN][49] (padded)
    float* s_w1  = s_W + BN * 49;        // 60 w1 + 3 b1

    const int tid = threadIdx.x;
    const int bp  = blockIdx.x;
    const int b   = bp >> 5;             // 32 point-blocks per batch
    const int n0  = (bp & 31) * 128;
    const int ob  = blockIdx.y * BN;

    if (tid < 60) s_w1[tid] = w1[tid];
    if (tid < 3)  s_w1[60 + tid] = b1[tid];

    // per-thread fixed (p,k) assignment; neighbor offsets kept in registers
    int joff[8];
    const float* fb = feat_in + (size_t)b * strideB;
#pragma unroll
    for (int r = 0; r < 8; r++) {
        int pid = tid + r * 256;
        int p = pid & 127, k = pid >> 7;
        int j = g_knn_idx[(((size_t)b * N_ + n0 + p) << 4) + k];
        joff[r] = j * strideJ;
    }
    __syncthreads();

    // stage tay[t*16+k][p] = b1[t] + sum_j basis[j]*w1[t][j]
#pragma unroll
    for (int r = 0; r < 8; r++) {
        int pid = tid + r * 256;
        int p = pid & 127, k = pid >> 7;
        const float* bas = g_basis + ((((size_t)b * N_ + n0 + p) << 4) + k) * 20;
        float t0 = s_w1[60], t1 = s_w1[61], t2 = s_w1[62];
#pragma unroll
        for (int j = 0; j < 20; j++) {
            float v = bas[j];
            t0 += v * s_w1[j];
            t1 += v * s_w1[20 + j];
            t2 += v * s_w1[40 + j];
        }
        s_tay[(0 * 16 + k) * 128 + p] = t0;
        s_tay[(1 * 16 + k) * 128 + p] = t1;
        s_tay[(2 * 16 + k) * 128 + p] = t2;
    }

    float acc[8][TN];
#pragma unroll
    for (int i = 0; i < 8; i++)
#pragma unroll
        for (int j = 0; j < TN; j++) acc[i][j] = 0.0f;

    const int tx = tid & 15;
    const int ty = tid >> 4;

    for (int c = 0; c < CIN; c++) {
        __syncthreads();

        // stage W chunk: s_W[o][t*16+k] = w2[(ob+o)*CIN*48 + c*48 + tkk]
        const float* w2c = w2 + (size_t)ob * (CIN * 48) + c * 48;
#pragma unroll 4
        for (int i = tid; i < BN * 48; i += 256) {
            int o = i / 48, tkk = i % 48;
            s_W[o * 49 + tkk] = w2c[(size_t)o * (CIN * 48) + tkk];
        }

        // stage E: gather gf and fuse with tay
#pragma unroll
        for (int r = 0; r < 8; r++) {
            int pid = tid + r * 256;
            int p = pid & 127, k = pid >> 7;
            float g = fb[joff[r] + c * strideC];
            s_E[(0 * 16 + k) * 128 + p] = g * s_tay[(0 * 16 + k) * 128 + p];
            s_E[(1 * 16 + k) * 128 + p] = g * s_tay[(1 * 16 + k) * 128 + p];
            s_E[(2 * 16 + k) * 128 + p] = g * s_tay[(2 * 16 + k) * 128 + p];
        }
        __syncthreads();

        // GEMM: acc[8][TN] += E[kk][p] * W[o][kk]
#pragma unroll
        for (int kk = 0; kk < 48; kk++) {
            float a[8];
            float4 a0 = *reinterpret_cast<const float4*>(&s_E[kk * 128 + ty * 8]);
            float4 a1 = *reinterpret_cast<const float4*>(&s_E[kk * 128 + ty * 8 + 4]);
            a[0] = a0.x; a[1] = a0.y; a[2] = a0.z; a[3] = a0.w;
            a[4] = a1.x; a[5] = a1.y; a[6] = a1.z; a[7] = a1.w;
            float bb[TN];
#pragma unroll
            for (int j = 0; j < TN; j++) bb[j] = s_W[(tx * TN + j) * 49 + kk];
#pragma unroll
            for (int i = 0; i < 8; i++)
#pragma unroll
                for (int j = 0; j < TN; j++)
                    acc[i][j] = fmaf(a[i], bb[j], acc[i][j]);
        }
    }

    // epilogue: bias + relu, store channel-major into point_feat region
#pragma unroll
    for (int j = 0; j < TN; j++) {
        int o = ob + tx * TN + j;
        float bias = b2[o];
        float* col = pf_out + ((size_t)b * 480 + o) * N_ + n0 + ty * 8;
        float4 v0, v1;
        v0.x = fmaxf(acc[0][j] + bias, 0.0f);
        v0.y = fmaxf(acc[1][j] + bias, 0.0f);
        v0.z = fmaxf(acc[2][j] + bias, 0.0f);
        v0.w = fmaxf(acc[3][j] + bias, 0.0f);
        v1.x = fmaxf(acc[4][j] + bias, 0.0f);
        v1.y = fmaxf(acc[5][j] + bias, 0.0f);
        v1.z = fmaxf(acc[6][j] + bias, 0.0f);
        v1.w = fmaxf(acc[7][j] + bias, 0.0f);
        reinterpret_cast<float4*>(col)[0] = v0;
        reinterpret_cast<float4*>(col)[1] = v1;
    }
}

// ---------------------------------------------------------------------------
// top-2 over N per (b, channel) row; one warp per row.
// ---------------------------------------------------------------------------
__global__ void top2_kernel(const float* __restrict__ pf, float* __restrict__ cat)
{
    int row  = blockIdx.x * 4 + (threadIdx.x >> 5);
    int lane = threadIdx.x & 31;
    if (row >= B_ * 480) return;

    const float* p = pf + (size_t)row * N_;
    float m1 = -FLT_MAX, m2 = -FLT_MAX;
    for (int i = lane; i < N_; i += 32) {
        float v = p[i];
        if (v > m1) { m2 = m1; m1 = v; }
        else if (v > m2) { m2 = v; }
    }
#pragma unroll
    for (int off = 16; off; off >>= 1) {
        float o1 = __shfl_down_sync(0xFFFFFFFFu, m1, off);
        float o2 = __shfl_down_sync(0xFFFFFFFFu, m2, off);
        float nm1 = fmaxf(m1, o1);
        float nm2 = fmaxf(fminf(m1, o1), fmaxf(m2, o2));
        m1 = nm1; m2 = nm2;
    }
    if (lane == 0) {
        int b = row / 480, ch = row % 480;
        cat[(size_t)b * 960 + ch * 2 + 0] = m1;
        cat[(size_t)b * 960 + ch * 2 + 1] = m2;
    }
}

// ---------------------------------------------------------------------------
// launch
// ---------------------------------------------------------------------------
static inline size_t layer_smem(int BN)
{
    return (size_t)(48 * 128 * 2 + BN * 49 + 64) * sizeof(float);
}

extern "C" void kernel_launch(void* const* d_in, const int* in_sizes, int n_in,
                              void* d_out, int out_size)
{
    (void)in_sizes; (void)n_in; (void)out_size;

    const float* pc   = (const float*)d_in[0];
    const float* w1_1 = (const float*)d_in[1];
    const float* b1_1 = (const float*)d_in[2];
    const float* w2_1 = (const float*)d_in[3];
    const float* b2_1 = (const float*)d_in[4];
    const float* w1_2 = (const float*)d_in[5];
    const float* b1_2 = (const float*)d_in[6];
    const float* w2_2 = (const float*)d_in[7];
    const float* b2_2 = (const float*)d_in[8];
    const float* w1_3 = (const float*)d_in[9];
    const float* b1_3 = (const float*)d_in[10];
    const float* w2_3 = (const float*)d_in[11];
    const float* b2_3 = (const float*)d_in[12];
    const float* w1_4 = (const float*)d_in[13];
    const float* b1_4 = (const float*)d_in[14];
    const float* w2_4 = (const float*)d_in[15];
    const float* b2_4 = (const float*)d_in[16];

    float* out = (float*)d_out;
    float* cat = out;               // (B, 960)
    float* pf  = out + B_ * 960;    // (B, 480, N) channel-major

    // opt-in to >48KB dynamic shared (idempotent, non-stream API)
    cudaFuncSetAttribute(layer_kernel<6, 32, 32>,
                         cudaFuncAttributeMaxDynamicSharedMemorySize, (int)layer_smem(32));
    cudaFuncSetAttribute(layer_kernel<32, 64, 64>,
                         cudaFuncAttributeMaxDynamicSharedMemorySize, (int)layer_smem(64));
    cudaFuncSetAttribute(layer_kernel<64, 128, 128>,
                         cudaFuncAttributeMaxDynamicSharedMemorySize, (int)layer_smem(128));
    cudaFuncSetAttribute(layer_kernel<128, 256, 128>,
                         cudaFuncAttributeMaxDynamicSharedMemorySize, (int)layer_smem(128));

    knn_basis_kernel<<<dim3(N_ / 128, B_), 128>>>(pc);

    // Layer 1: input = pc (B,N,6) point-major; output channels [0,32)
    layer_kernel<6, 32, 32><<<dim3(128, 1), 256, layer_smem(32)>>>(
        pc, N_ * 6, 6, 1, w1_1, b1_1, w2_1, b2_1, pf + (size_t)0 * N_);

    // Layer 2: input channels [0,32); output [32,96)
    layer_kernel<32, 64, 64><<<dim3(128, 1), 256, layer_smem(64)>>>(
        pf, 480 * N_, 1, N_, w1_2, b1_2, w2_2, b2_2, pf + (size_t)32 * N_);

    // Layer 3: input [32,96); output [96,224)
    layer_kernel<64, 128, 128><<<dim3(128, 1), 256, layer_smem(128)>>>(
        pf + (size_t)32 * N_, 480 * N_, 1, N_, w1_3, b1_3, w2_3, b2_3,
        pf + (size_t)96 * N_);

    // Layer 4: input [96,224); output [224,480)
    layer_kernel<128, 256, 128><<<dim3(128, 2), 256, layer_smem(128)>>>(
        pf + (size_t)96 * N_, 480 * N_, 1, N_, w1_4, b1_4, w2_4, b2_4,
        pf + (size_t)224 * N_);

    top2_kernel<<<(B_ * 480) / 4, 128>>>(pf, cat);
}

// round 4
// speedup vs baseline: 1.5454x; 1.5454x over previous
#include <cuda_runtime.h>
#include <cuda_bf16.h>
#include <float.h>
#include <stdint.h>

#define B_ 4
#define N_ 4096
#define K_ 16

// ---------------- device scratch (allocation-free rule) ----------------
__device__ int      g_knn_idx[B_ * N_ * K_];
__device__ float    g_basis[B_ * N_ * K_ * 20];
__device__ float    g_fT1[B_ * N_ * 32];    // layer1 out, point-major
__device__ float    g_fT2[B_ * N_ * 64];
__device__ float    g_fT3[B_ * N_ * 128];
// W in mma-B-fragment layout, bf16 hi/lo planes:
// [kb][nb][pl][lane][2] u32 ; L2 @0 (98304), L3 @98304 (393216), L4 @491520 (1572864)
__device__ uint32_t g_wfrag[2064384];

// ---------------- mma / ldmatrix wrappers (baseline PTX, sm_80+) -------
__device__ __forceinline__ uint32_t smem_u32(const void* p) {
    uint32_t a;
    asm("{ .reg .u64 t; cvta.to.shared.u64 t, %1; cvt.u32.u64 %0, t; }" : "=r"(a) : "l"(p));
    return a;
}
__device__ __forceinline__ void ldmatrix_x4(uint32_t* r, uint32_t addr) {
    asm volatile("ldmatrix.sync.aligned.m8n8.x4.shared.b16 {%0,%1,%2,%3}, [%4];"
                 : "=r"(r[0]), "=r"(r[1]), "=r"(r[2]), "=r"(r[3]) : "r"(addr));
}
__device__ __forceinline__ void mma_bf16(float* d, const uint32_t* a, uint32_t b0, uint32_t b1) {
    asm volatile("mma.sync.aligned.m16n8k16.row.col.f32.bf16.bf16.f32 "
                 "{%0,%1,%2,%3}, {%4,%5,%6,%7}, {%8,%9}, {%0,%1,%2,%3};"
                 : "+f"(d[0]), "+f"(d[1]), "+f"(d[2]), "+f"(d[3])
                 : "r"(a[0]), "r"(a[1]), "r"(a[2]), "r"(a[3]), "r"(b0), "r"(b1));
}

// ---------------- KNN + Taylor basis (validated in R1) ----------------
__global__ void knn_basis_kernel(const float* __restrict__ pc)
{
    const int b = blockIdx.y;
    const int n = blockIdx.x * 128 + threadIdx.x;
    const float* pcb = pc + (size_t)b * N_ * 6;

    const float qx = pcb[n * 6 + 0], qy = pcb[n * 6 + 1], qz = pcb[n * 6 + 2];
    const float qsq = __fadd_rn(__fadd_rn(__fmul_rn(qx, qx), __fmul_rn(qy, qy)),
                                __fmul_rn(qz, qz));
    float dist[K_]; int nid[K_];
#pragma unroll
    for (int i = 0; i < K_; i++) { dist[i] = FLT_MAX; nid[i] = 0; }

    __shared__ float4 s_c[1024];
    for (int tile = 0; tile < N_; tile += 1024) {
        __syncthreads();
        for (int i = threadIdx.x; i < 1024; i += 128) {
            int j = tile + i;
            float x = pcb[j * 6 + 0], y = pcb[j * 6 + 1], z = pcb[j * 6 + 2];
            float sq = __fadd_rn(__fadd_rn(__fmul_rn(x, x), __fmul_rn(y, y)),
                                 __fmul_rn(z, z));
            s_c[i] = make_float4(x, y, z, sq);
        }
        __syncthreads();
        for (int i = 0; i < 1024; i++) {
            float4 c = s_c[i];
            float dot = __fadd_rn(__fadd_rn(__fmul_rn(qx, c.x), __fmul_rn(qy, c.y)),
                                  __fmul_rn(qz, c.z));
            float d2 = __fsub_rn(__fadd_rn(qsq, c.w), __fmul_rn(2.0f, dot));
            if (d2 < dist[K_ - 1]) {
                dist[K_ - 1] = d2; nid[K_ - 1] = tile + i;
#pragma unroll
                for (int j = K_ - 1; j > 0; --j)
                    if (dist[j] < dist[j - 1]) {
                        float td = dist[j]; dist[j] = dist[j - 1]; dist[j - 1] = td;
                        int ti = nid[j]; nid[j] = nid[j - 1]; nid[j - 1] = ti;
                    }
            }
        }
    }
    int*   iout = g_knn_idx + ((size_t)b * N_ + n) * K_;
    float* bout = g_basis + (((size_t)b * N_ + n) * K_) * 20;
#pragma unroll
    for (int k = 0; k < K_; k++) {
        int j = nid[k]; iout[k] = j;
        float x = pcb[j * 6 + 0] - qx, y = pcb[j * 6 + 1] - qy, z = pcb[j * 6 + 2] - qz;
        float* o = bout + k * 20;
        o[0] = 1.0f; o[1] = x; o[2] = y; o[3] = z;
        o[4] = x * x; o[5] = x * y; o[6] = x * z; o[7] = y * y; o[8] = y * z; o[9] = z * z;
        o[10] = x * x * x; o[11] = x * x * y; o[12] = x * x * z; o[13] = x * y * y;
        o[14] = x * y * z; o[15] = x * z * z; o[16] = y * y * y; o[17] = y * y * z;
        o[18] = y * z * z; o[19] = z * z * z;
    }
}

// ---------------- scalar layer 1 (CIN=6) -------------------------------
__global__ void __launch_bounds__(256, 2)
layer1_kernel(const float* __restrict__ pc,
              const float* __restrict__ w1, const float* __restrict__ b1,
              const float* __restrict__ w2, const float* __restrict__ b2,
              float* __restrict__ pf_out)
{
    constexpr int CIN = 6, COUT = 32, BN = 32, TN = BN / 16;
    extern __shared__ float smemf[];
    float* s_tay = smemf;
    float* s_E   = s_tay + 48 * 128;
    float* s_W   = s_E + 48 * 128;
    float* s_w1  = s_W + BN * 49;

    const int tid = threadIdx.x;
    const int b   = blockIdx.x >> 5;
    const int n0  = (blockIdx.x & 31) * 128;

    if (tid < 60) s_w1[tid] = w1[tid];
    if (tid < 3)  s_w1[60 + tid] = b1[tid];

    int joff[8];
    const float* fb = pc + (size_t)b * N_ * 6;
#pragma unroll
    for (int r = 0; r < 8; r++) {
        int pid = tid + r * 256, p = pid & 127, k = pid >> 7;
        joff[r] = g_knn_idx[(((size_t)b * N_ + n0 + p) << 4) + k] * 6;
    }
    __syncthreads();
#pragma unroll
    for (int r = 0; r < 8; r++) {
        int pid = tid + r * 256, p = pid & 127, k = pid >> 7;
        const float* bas = g_basis + ((((size_t)b * N_ + n0 + p) << 4) + k) * 20;
        float t0 = s_w1[60], t1 = s_w1[61], t2 = s_w1[62];
#pragma unroll
        for (int j = 0; j < 20; j++) {
            float v = bas[j];
            t0 += v * s_w1[j]; t1 += v * s_w1[20 + j]; t2 += v * s_w1[40 + j];
        }
        s_tay[k * 128 + p] = t0;
        s_tay[(16 + k) * 128 + p] = t1;
        s_tay[(32 + k) * 128 + p] = t2;
    }

    float acc[8][TN];
#pragma unroll
    for (int i = 0; i < 8; i++)
#pragma unroll
        for (int j = 0; j < TN; j++) acc[i][j] = 0.0f;

    const int tx = tid & 15, ty = tid >> 4;
    for (int c = 0; c < CIN; c++) {
        __syncthreads();
        const float* w2c = w2 + c * 48;
        for (int i = tid; i < BN * 48; i += 256) {
            int o = i / 48, tkk = i % 48;
            s_W[o * 49 + tkk] = w2c[(size_t)o * (CIN * 48) + tkk];
        }
#pragma unroll
        for (int r = 0; r < 8; r++) {
            int pid = tid + r * 256, p = pid & 127, k = pid >> 7;
            float g = fb[joff[r] + c];
            s_E[k * 128 + p] = g * s_tay[k * 128 + p];
            s_E[(16 + k) * 128 + p] = g * s_tay[(16 + k) * 128 + p];
            s_E[(32 + k) * 128 + p] = g * s_tay[(32 + k) * 128 + p];
        }
        __syncthreads();
#pragma unroll
        for (int kk = 0; kk < 48; kk++) {
            float a[8];
            float4 a0 = *reinterpret_cast<const float4*>(&s_E[kk * 128 + ty * 8]);
            float4 a1 = *reinterpret_cast<const float4*>(&s_E[kk * 128 + ty * 8 + 4]);
            a[0] = a0.x; a[1] = a0.y; a[2] = a0.z; a[3] = a0.w;
            a[4] = a1.x; a[5] = a1.y; a[6] = a1.z; a[7] = a1.w;
            float bb[TN];
#pragma unroll
            for (int j = 0; j < TN; j++) bb[j] = s_W[(tx * TN + j) * 49 + kk];
#pragma unroll
            for (int i = 0; i < 8; i++)
#pragma unroll
                for (int j = 0; j < TN; j++) acc[i][j] = fmaf(a[i], bb[j], acc[i][j]);
        }
    }
#pragma unroll
    for (int j = 0; j < TN; j++) {
        int o = tx * TN + j;
        float bias = b2[o];
        float* col = pf_out + ((size_t)b * 480 + o) * N_ + n0 + ty * 8;
#pragma unroll
        for (int i = 0; i < 8; i++) {
            float v = fmaxf(acc[i][j] + bias, 0.0f);
            col[i] = v;
            g_fT1[((size_t)b * N_ + n0 + ty * 8 + i) * COUT + o] = v;
        }
    }
}

// ---------------- W fragment prep (split + frag layout) ----------------
template<int CIN, int NB, int WOFF>
__global__ void prep_w_kernel(const float* __restrict__ w2)
{
    constexpr int KB = CIN * 3;
    int flat = blockIdx.x * 256 + threadIdx.x;
    if (flat >= KB * NB * 64) return;
    int lane2 = flat & 63;
    int lane = lane2 >> 1, r = lane2 & 1;
    int nb = (flat >> 6) % NB;
    int kb = flat / (64 * NB);

    int n = nb * 8 + (lane >> 2);
    int k0 = (lane & 3) * 2 + r * 8;
    float v[2];
#pragma unroll
    for (int h = 0; h < 2; h++) {
        int kd = kb * 16 + k0 + h;
        int c = kd / 48, t = (kd / 16) % 3, k = kd & 15;
        v[h] = w2[((size_t)n * (CIN * 3) + c * 3 + t) * 16 + k];
    }
    __nv_bfloat162 hi = __floats2bfloat162_rn(v[0], v[1]);
    float2 hf = __bfloat1622float2(hi);
    __nv_bfloat162 lo = __floats2bfloat162_rn(v[0] - hf.x, v[1] - hf.y);
    uint32_t idx = (uint32_t)((kb * NB + nb) * 2) * 64 + lane * 2 + r;
    g_wfrag[WOFF + idx]      = *(uint32_t*)&hi;
    g_wfrag[WOFF + idx + 64] = *(uint32_t*)&lo;
}

// ---------------- tensor-core layer (layers 2-4) -----------------------
// CTA: 128 points x 64 outs; 8 warps (2M x 4N), warp tile 64x16.
// K consumed 2 input channels (96 cols) per round; E generated on the fly.
// SMEM: s_B 24576B | s_E_hi 26624B | s_E_lo 26624B  (stride 208B rows)
template<int CIN, int NB_ALL, int LAYER>
__global__ void __launch_bounds__(256, 2)
tlayer_kernel(const float* __restrict__ w1, const float* __restrict__ b1,
              const float* __restrict__ b2, float* __restrict__ pf_out)
{
    constexpr int COUT = NB_ALL * 8;
    constexpr int WOFF = (LAYER == 2) ? 0 : (LAYER == 3) ? 98304 : 491520;

    const float* fT_in = (LAYER == 2) ? g_fT1 : (LAYER == 3) ? g_fT2 : g_fT3;
    float* fT_out = (LAYER == 2) ? g_fT2 : (LAYER == 3) ? g_fT3 : (float*)0;

    extern __shared__ char smem[];
    uint32_t* sB  = (uint32_t*)smem;                 // 6144 u32
    uint32_t* eh  = (uint32_t*)(smem + 24576);       // 128 x 52 u32
    uint32_t* el  = (uint32_t*)(smem + 51200);
    const uint32_t sb_addr = smem_u32(smem);
    const uint32_t EH = sb_addr + 24576, EL = sb_addr + 51200;

    const int tid  = threadIdx.x;
    const int lane = tid & 31;
    const int wid  = tid >> 5;
    const int wm   = wid >> 2;        // 0..1
    const int wn   = wid & 3;         // 0..3
    const int b    = blockIdx.x >> 5;
    const int n0   = (blockIdx.x & 31) * 128;
    const int by   = blockIdx.y;      // N-split (64 out-ch each)

    // prologue: per-thread 8 (p,k) items: p = tid&127, k = kq*8 + i
    const int p  = tid & 127;
    const int kq = tid >> 7;
    int   jof[8];
    float tay[8][3];
#pragma unroll
    for (int i = 0; i < 8; i++) {
        int k = kq * 8 + i;
        size_t pkid = (((size_t)b * N_ + n0 + p) << 4) + k;
        jof[i] = g_knn_idx[pkid] * CIN;
        const float4* bas = (const float4*)(g_basis + pkid * 20);
        float4 b0 = __ldg(bas), b1v = __ldg(bas + 1), b2v = __ldg(bas + 2),
               b3 = __ldg(bas + 3), b4 = __ldg(bas + 4);
        float bs[20] = { b0.x,b0.y,b0.z,b0.w, b1v.x,b1v.y,b1v.z,b1v.w,
                         b2v.x,b2v.y,b2v.z,b2v.w, b3.x,b3.y,b3.z,b3.w,
                         b4.x,b4.y,b4.z,b4.w };
#pragma unroll
        for (int t = 0; t < 3; t++) {
            float acc = __ldg(&b1[t]);
#pragma unroll
            for (int j = 0; j < 20; j++) acc += bs[j] * __ldg(&w1[t * 20 + j]);
            tay[i][t] = acc;
        }
    }

    float acc[4][2][4];
#pragma unroll
    for (int m = 0; m < 4; m++)
#pragma unroll
        for (int n = 0; n < 2; n++)
#pragma unroll
            for (int r = 0; r < 4; r++) acc[m][n][r] = 0.0f;

    const float* fb = fT_in + (size_t)b * N_ * CIN;
    const uint32_t* wf = g_wfrag + WOFF;

    for (int g = 0; g < CIN / 2; g++) {
        const int c0 = 2 * g;

        // stage B fragments: 6 kb-chunks of 1024 u32 (8 nb x 2 pl x 64)
        {
            const uint4* wf4 = (const uint4*)wf;
            uint4* sB4 = (uint4*)sB;
#pragma unroll
            for (int r = 0; r < 6; r++) {
                int idx = tid + r * 256;          // 1536 uint4 total
                int kb = idx >> 8, off = idx & 255;
                sB4[idx] = __ldg(&wf4[(size_t)((g * 6 + kb) * NB_ALL + by * 8) * 32 + off]);
            }
        }
        // generate E hi/lo (2 slices x 3 t x 16 k)  — pairs of k share a float2 col-pair
#pragma unroll
        for (int pr = 0; pr < 4; pr++) {
            int i0 = 2 * pr, i1 = 2 * pr + 1;
            float2 ga = __ldg((const float2*)(fb + jof[i0] + c0));
            float2 gb = __ldg((const float2*)(fb + jof[i1] + c0));
#pragma unroll
            for (int t = 0; t < 3; t++) {
                float ta = tay[i0][t], tb = tay[i1][t];
#pragma unroll
                for (int cl = 0; cl < 2; cl++) {
                    float v0 = (cl ? ga.y : ga.x) * ta;
                    float v1 = (cl ? gb.y : gb.x) * tb;
                    __nv_bfloat162 hi = __floats2bfloat162_rn(v0, v1);
                    float2 hf = __bfloat1622float2(hi);
                    __nv_bfloat162 lo = __floats2bfloat162_rn(v0 - hf.x, v1 - hf.y);
                    int col = cl * 48 + t * 16 + kq * 8 + 2 * pr;
                    eh[p * 52 + (col >> 1)] = *(uint32_t*)&hi;
                    el[p * 52 + (col >> 1)] = *(uint32_t*)&lo;
                }
            }
        }
        __syncthreads();

        // mma over 6 k16 blocks, 3-product bf16 split
#pragma unroll 1
        for (int kb = 0; kb < 6; kb++) {
            uint32_t ah[4][4], al[4][4];
#pragma unroll
            for (int ms = 0; ms < 4; ms++) {
                uint32_t rowb = (wm * 64 + ms * 16 + (lane & 15)) * 208 +
                                kb * 32 + (lane >> 4) * 16;
                ldmatrix_x4(ah[ms], EH + rowb);
                ldmatrix_x4(al[ms], EL + rowb);
            }
#pragma unroll
            for (int ns = 0; ns < 2; ns++) {
                int nb = wn * 2 + ns;
                const uint2* bp = (const uint2*)(sB + ((kb * 8 + nb) * 2) * 64);
                uint2 bh = bp[lane];
                uint2 bl = bp[32 + lane];
#pragma unroll
                for (int ms = 0; ms < 4; ms++) {
                    mma_bf16(acc[ms][ns], ah[ms], bh.x, bh.y);
                    mma_bf16(acc[ms][ns], ah[ms], bl.x, bl.y);
                    mma_bf16(acc[ms][ns], al[ms], bh.x, bh.y);
                }
            }
        }
        __syncthreads();
    }

    // epilogue: bias + relu -> pf (channel-major) and fT (point-major)
    const int row = lane >> 2, col2 = (lane & 3) * 2;
#pragma unroll
    for (int ns = 0; ns < 2; ns++) {
        int och0 = by * 64 + wn * 16 + ns * 8 + col2;
        float bi0 = __ldg(&b2[och0]), bi1 = __ldg(&b2[och0 + 1]);
#pragma unroll
        for (int ms = 0; ms < 4; ms++) {
            int np0 = n0 + wm * 64 + ms * 16 + row;
            float v00 = fmaxf(acc[ms][ns][0] + bi0, 0.0f);
            float v01 = fmaxf(acc[ms][ns][1] + bi1, 0.0f);
            float v10 = fmaxf(acc[ms][ns][2] + bi0, 0.0f);
            float v11 = fmaxf(acc[ms][ns][3] + bi1, 0.0f);
            pf_out[((size_t)b * 480 + och0) * N_ + np0]           = v00;
            pf_out[((size_t)b * 480 + och0 + 1) * N_ + np0]       = v01;
            pf_out[((size_t)b * 480 + och0) * N_ + np0 + 8]       = v10;
            pf_out[((size_t)b * 480 + och0 + 1) * N_ + np0 + 8]   = v11;
            if (fT_out) {
                fT_out[((size_t)b * N_ + np0) * COUT + och0]         = v00;
                fT_out[((size_t)b * N_ + np0) * COUT + och0 + 1]     = v01;
                fT_out[((size_t)b * N_ + np0 + 8) * COUT + och0]     = v10;
                fT_out[((size_t)b * N_ + np0 + 8) * COUT + och0 + 1] = v11;
            }
        }
    }
}

// ---------------- top-2 ----------------
__global__ void top2_kernel(const float* __restrict__ pf, float* __restrict__ cat)
{
    int row = blockIdx.x * 4 + (threadIdx.x >> 5);
    int lane = threadIdx.x & 31;
    if (row >= B_ * 480) return;
    const float* p = pf + (size_t)row * N_;
    float m1 = -FLT_MAX, m2 = -FLT_MAX;
    for (int i = lane; i < N_; i += 32) {
        float v = p[i];
        if (v > m1) { m2 = m1; m1 = v; }
        else if (v > m2) m2 = v;
    }
#pragma unroll
    for (int off = 16; off; off >>= 1) {
        float o1 = __shfl_down_sync(0xFFFFFFFFu, m1, off);
        float o2 = __shfl_down_sync(0xFFFFFFFFu, m2, off);
        float nm1 = fmaxf(m1, o1);
        float nm2 = fmaxf(fminf(m1, o1), fmaxf(m2, o2));
        m1 = nm1; m2 = nm2;
    }
    if (lane == 0) {
        int b = row / 480, ch = row % 480;
        cat[(size_t)b * 960 + ch * 2 + 0] = m1;
        cat[(size_t)b * 960 + ch * 2 + 1] = m2;
    }
}

// ---------------- launch ----------------
extern "C" void kernel_launch(void* const* d_in, const int* in_sizes, int n_in,
                              void* d_out, int out_size)
{
    (void)in_sizes; (void)n_in; (void)out_size;
    const float* pc   = (const float*)d_in[0];
    const float* w1_1 = (const float*)d_in[1];
    const float* b1_1 = (const float*)d_in[2];
    const float* w2_1 = (const float*)d_in[3];
    const float* b2_1 = (const float*)d_in[4];
    const float* w1_2 = (const float*)d_in[5];
    const float* b1_2 = (const float*)d_in[6];
    const float* w2_2 = (const float*)d_in[7];
    const float* b2_2 = (const float*)d_in[8];
    const float* w1_3 = (const float*)d_in[9];
    const float* b1_3 = (const float*)d_in[10];
    const float* w2_3 = (const float*)d_in[11];
    const float* b2_3 = (const float*)d_in[12];
    const float* w1_4 = (const float*)d_in[13];
    const float* b1_4 = (const float*)d_in[14];
    const float* w2_4 = (const float*)d_in[15];
    const float* b2_4 = (const float*)d_in[16];

    float* out = (float*)d_out;
    float* cat = out;
    float* pf  = out + B_ * 960;

    size_t sm1 = (size_t)(48 * 128 * 2 + 32 * 49 + 64) * sizeof(float);
    cudaFuncSetAttribute(layer1_kernel,
                         cudaFuncAttributeMaxDynamicSharedMemorySize, (int)sm1);
    const size_t SMT = 77824;
    cudaFuncSetAttribute(tlayer_kernel<32, 8, 2>,
                         cudaFuncAttributeMaxDynamicSharedMemorySize, (int)SMT);
    cudaFuncSetAttribute(tlayer_kernel<64, 16, 3>,
                         cudaFuncAttributeMaxDynamicSharedMemorySize, (int)SMT);
    cudaFuncSetAttribute(tlayer_kernel<128, 32, 4>,
                         cudaFuncAttributeMaxDynamicSharedMemorySize, (int)SMT);

    prep_w_kernel<32, 8, 0><<<(96 * 8 * 64 + 255) / 256, 256>>>(w2_2);
    prep_w_kernel<64, 16, 98304><<<(192 * 16 * 64 + 255) / 256, 256>>>(w2_3);
    prep_w_kernel<128, 32, 491520><<<(384 * 32 * 64 + 255) / 256, 256>>>(w2_4);

    knn_basis_kernel<<<dim3(N_ / 128, B_), 128>>>(pc);

    layer1_kernel<<<128, 256, sm1>>>(pc, w1_1, b1_1, w2_1, b2_1, pf);

    tlayer_kernel<32, 8, 2><<<dim3(128, 1), 256, SMT>>>(
        w1_2, b1_2, b2_2, pf + (size_t)32 * N_);
    tlayer_kernel<64, 16, 3><<<dim3(128, 2), 256, SMT>>>(
        w1_3, b1_3, b2_3, pf + (size_t)96 * N_);
    tlayer_kernel<128, 32, 4><<<dim3(128, 4), 256, SMT>>>(
        w1_4, b1_4, b2_4, pf + (size_t)224 * N_);

    top2_kernel<<<(B_ * 480) / 4, 128>>>(pf, cat);
}